// round 2
// baseline (speedup 1.0000x reference)
#include <cuda_runtime.h>
#include <math.h>

// Problem constants
#define BHC   16      // b*h
#define NSEQ  4096
#define DDIM  64
#define MFEAT 256
#define EDIM  64
#define CHK   128
#define NCH   32      // NSEQ / CHK

#define NORM_F   0.35355339059327373f   // 64^-0.25
#define DIAG_C   0.0625f                // 0.5 * NORM^2
#define RATIO_F  0.0625f                // 256^-0.5
#define EPS_KF   1e-4f
#define EPS_DF   1e-6f

// Scratch (static device globals — no allocation allowed)
__device__ float    g_phi_q[BHC * NSEQ * MFEAT];        // 64 MiB
__device__ float    g_phi_k[BHC * NSEQ * MFEAT];        // 64 MiB (dd-diag then phi)
__device__ float    g_S[BHC * NCH * EDIM * MFEAT];      // 32 MiB, layout [bh][c][e][m]
__device__ float    g_z[BHC * NCH * MFEAT];             // 512 KiB
__device__ unsigned g_kmax[BHC];

// ---------------------------------------------------------------------------
__global__ void init_kmax_kernel() {
    if (threadIdx.x < BHC) g_kmax[threadIdx.x] = 0u;
}

// ---------------------------------------------------------------------------
// phi kernel: 16 rows per block, 256 threads. proj staged transposed+scaled in smem.
// is_query==1: fused rowmax + exp -> g_phi_q
// is_query==0: writes (dd - diag) -> g_phi_k, atomicMax of dd per bh
#define PHI_SMEM_FLOATS (64 * 257 + 16 * 64)
__global__ void phi_kernel(const float* __restrict__ data,
                           const float* __restrict__ proj,
                           int is_query) {
    extern __shared__ float sm[];
    float* proj_s = sm;                 // [64][257] transposed, pre-scaled
    float* q_s    = sm + 64 * 257;      // [16][64]
    __shared__ float wmax_s[8];

    float* out = is_query ? g_phi_q : g_phi_k;
    const int tid = threadIdx.x;
    const int row0 = blockIdx.x * 16;

    // load proj [256][64] -> proj_s[d][j] (stride 257, conflict-free), fold NORM
    #pragma unroll 4
    for (int i = 0; i < 64; ++i) {
        int idx = tid + i * 256;
        int j = idx >> 6, d = idx & 63;
        proj_s[d * 257 + j] = proj[idx] * NORM_F;
    }
    // load 16 data rows
    #pragma unroll
    for (int i = 0; i < 4; ++i) {
        int idx = tid + i * 256;
        q_s[idx] = data[(size_t)row0 * DDIM + idx];
    }
    __syncthreads();

    const int w = tid >> 5, lane = tid & 31;
    float wmax = -3.4e38f;

    #pragma unroll
    for (int rr = 0; rr < 2; ++rr) {
        const int rl = w * 2 + rr;
        const size_t rowg = (size_t)row0 + rl;
        float acc[8];
        #pragma unroll
        for (int jj = 0; jj < 8; ++jj) acc[jj] = 0.f;
        float ss = 0.f;
        #pragma unroll 4
        for (int d = 0; d < 64; ++d) {
            float qv = q_s[rl * 64 + d];
            ss = fmaf(qv, qv, ss);
            #pragma unroll
            for (int jj = 0; jj < 8; ++jj)
                acc[jj] = fmaf(qv, proj_s[d * 257 + jj * 32 + lane], acc[jj]);
        }
        const float diag = DIAG_C * ss;
        float m8 = acc[0];
        #pragma unroll
        for (int jj = 1; jj < 8; ++jj) m8 = fmaxf(m8, acc[jj]);

        if (is_query) {
            #pragma unroll
            for (int o = 16; o > 0; o >>= 1)
                m8 = fmaxf(m8, __shfl_xor_sync(0xffffffffu, m8, o));
            #pragma unroll
            for (int jj = 0; jj < 8; ++jj)
                out[rowg * MFEAT + jj * 32 + lane] =
                    RATIO_F * (expf(acc[jj] - diag - m8) + EPS_KF);
        } else {
            #pragma unroll
            for (int jj = 0; jj < 8; ++jj)
                out[rowg * MFEAT + jj * 32 + lane] = acc[jj] - diag;
            wmax = fmaxf(wmax, m8);
        }
    }

    if (!is_query) {
        #pragma unroll
        for (int o = 16; o > 0; o >>= 1)
            wmax = fmaxf(wmax, __shfl_xor_sync(0xffffffffu, wmax, o));
        if (lane == 0) wmax_s[w] = wmax;
        __syncthreads();
        if (tid == 0) {
            float bm = wmax_s[0];
            #pragma unroll
            for (int i = 1; i < 8; ++i) bm = fmaxf(bm, wmax_s[i]);
            unsigned u = __float_as_uint(bm);
            u = (u & 0x80000000u) ? ~u : (u | 0x80000000u);
            atomicMax(&g_kmax[blockIdx.x >> 8], u);   // 256 blocks per bh
        }
    }
}

// ---------------------------------------------------------------------------
// finalize phi_k: elementwise exp with global per-bh max
__global__ void finalize_k_kernel() {
    const size_t n4 = (size_t)BHC * NSEQ * MFEAT / 4;
    float4* p = reinterpret_cast<float4*>(g_phi_k);
    const size_t stride = (size_t)gridDim.x * blockDim.x;
    for (size_t t = (size_t)blockIdx.x * blockDim.x + threadIdx.x; t < n4; t += stride) {
        size_t bh = (t * 4) / ((size_t)NSEQ * MFEAT);
        unsigned u = g_kmax[bh];
        float mx = __uint_as_float((u & 0x80000000u) ? (u ^ 0x80000000u) : ~u);
        float4 v = p[t];
        v.x = RATIO_F * (expf(v.x - mx) + EPS_KF);
        v.y = RATIO_F * (expf(v.y - mx) + EPS_KF);
        v.z = RATIO_F * (expf(v.z - mx) + EPS_KF);
        v.w = RATIO_F * (expf(v.w - mx) + EPS_KF);
        p[t] = v;
    }
}

// ---------------------------------------------------------------------------
// per-chunk sums: S_c = k_c^T v_c (stored transposed [e][m]), z_c = colsum(k_c)
__global__ void chunk_sums_kernel(const float* __restrict__ vin) {
    __shared__ float4 v4[CHK * 16];     // v chunk [128][64] as float4
    const int tid = threadIdx.x;
    const int cix = blockIdx.x;
    const size_t base_row = (size_t)(cix / NCH) * NSEQ + (size_t)(cix % NCH) * CHK;

    const float4* vg4 = reinterpret_cast<const float4*>(vin) + base_row * 16;
    #pragma unroll
    for (int i = 0; i < 8; ++i) v4[tid + i * 256] = vg4[tid + i * 256];
    __syncthreads();

    const int m = tid;
    float4 acc[16];
    #pragma unroll
    for (int e = 0; e < 16; ++e) acc[e] = make_float4(0.f, 0.f, 0.f, 0.f);
    float z = 0.f;
    const float* gk = g_phi_k + base_row * MFEAT;
    #pragma unroll 2
    for (int r = 0; r < CHK; ++r) {
        float km = gk[(size_t)r * MFEAT + m];
        z += km;
        #pragma unroll
        for (int e = 0; e < 16; ++e) {
            float4 vv = v4[r * 16 + e];
            acc[e].x = fmaf(km, vv.x, acc[e].x);
            acc[e].y = fmaf(km, vv.y, acc[e].y);
            acc[e].z = fmaf(km, vv.z, acc[e].z);
            acc[e].w = fmaf(km, vv.w, acc[e].w);
        }
    }
    float* Sg = g_S + (size_t)cix * MFEAT * EDIM;   // [e][m]
    #pragma unroll
    for (int e = 0; e < 16; ++e) {
        Sg[(e * 4 + 0) * MFEAT + m] = acc[e].x;
        Sg[(e * 4 + 1) * MFEAT + m] = acc[e].y;
        Sg[(e * 4 + 2) * MFEAT + m] = acc[e].z;
        Sg[(e * 4 + 3) * MFEAT + m] = acc[e].w;
    }
    g_z[(size_t)cix * MFEAT + m] = z;
}

// ---------------------------------------------------------------------------
// in-place exclusive prefix over the 32 chunks, per (bh, e, m) / (bh, m)
__global__ void prefix_kernel() {
    const int idx = blockIdx.x * blockDim.x + threadIdx.x;
    const int T1 = BHC * MFEAT * EDIM;   // 262144
    if (idx < T1) {
        int bh = idx / (MFEAT * EDIM);
        int rem = idx % (MFEAT * EDIM);
        size_t base = (size_t)bh * NCH * MFEAT * EDIM + rem;
        float run = 0.f;
        #pragma unroll
        for (int c = 0; c < NCH; ++c) {
            size_t p = base + (size_t)c * MFEAT * EDIM;
            float t = g_S[p]; g_S[p] = run; run += t;
        }
    } else if (idx < T1 + BHC * MFEAT) {
        int j = idx - T1;
        int bh = j / MFEAT;
        int rem = j % MFEAT;
        size_t base = (size_t)bh * NCH * MFEAT + rem;
        float run = 0.f;
        #pragma unroll
        for (int c = 0; c < NCH; ++c) {
            size_t p = base + (size_t)c * MFEAT;
            float t = g_z[p]; g_z[p] = run; run += t;
        }
    }
}

// ---------------------------------------------------------------------------
// output kernel: per (bh, chunk):
//   scores = tril(phiq_c @ phik_c^T)            [128][128]
//   out    = (phiq_c @ S_prev + scores @ v_c) / denom
//   denom[r] = phiq_r . z_prev + rowsum(scores[r]) + EPS * sum(phiq_r)
#define SC_OFF   0
#define QS_OFF   (128 * 132)
#define KS_OFF   (QS_OFF + 128 * 68)
#define SS_OFF   (KS_OFF + 128 * 68)
#define ZS_OFF   (SS_OFF + 64 * 68)
#define QZ_OFF   (ZS_OFF + 256)
#define SQ_OFF   (QZ_OFF + 128)
#define S2_OFF   (SQ_OFF + 128)
#define OUT_SMEM_FLOATS (S2_OFF + 256)

__global__ void out_kernel(const float* __restrict__ vin, float* __restrict__ outp) {
    extern __shared__ float sm[];
    float* sc  = sm + SC_OFF;    // [128][132] masked scores
    float* qs  = sm + QS_OFF;    // [128][68] q tile
    float* ks  = sm + KS_OFF;    // [128][68] k tile, then v
    float* Ss  = sm + SS_OFF;    // [64][68]  S tile ([e][m])
    float* zs  = sm + ZS_OFF;    // [256] z_prev
    float* qz  = sm + QZ_OFF;    // [128] q.z_prev
    float* sq  = sm + SQ_OFF;    // [128] sum(q)
    float* ss2 = sm + S2_OFF;    // [256] score rowsum halves

    const int tid = threadIdx.x;
    const int cix = blockIdx.x;
    const size_t base_row = (size_t)(cix / NCH) * NSEQ + (size_t)(cix % NCH) * CHK;
    const float* gq = g_phi_q + base_row * MFEAT;
    const float* gk = g_phi_k + base_row * MFEAT;

    zs[tid] = g_z[(size_t)cix * MFEAT + tid];

    // ---- Phase 1: scores ----
    // thread -> 8x8 tile: rows r0..r0+7 contiguous, cols j0 + jj*16 (strided)
    const int r0 = (tid >> 4) << 3;
    const int j0 = tid & 15;
    float acc[64];
    #pragma unroll
    for (int i = 0; i < 64; ++i) acc[i] = 0.f;
    float qzr = 0.f, sqr = 0.f;

    const float4* gq4 = reinterpret_cast<const float4*>(gq);
    const float4* gk4 = reinterpret_cast<const float4*>(gk);

    for (int mt = 0; mt < 4; ++mt) {
        __syncthreads();
        #pragma unroll
        for (int i = 0; i < 8; ++i) {
            int idx = tid + i * 256;
            int r = idx >> 4, c4 = idx & 15;
            *reinterpret_cast<float4*>(qs + r * 68 + c4 * 4) = gq4[(size_t)r * 64 + mt * 16 + c4];
            *reinterpret_cast<float4*>(ks + r * 68 + c4 * 4) = gk4[(size_t)r * 64 + mt * 16 + c4];
        }
        __syncthreads();
        #pragma unroll 4
        for (int mm = 0; mm < 64; ++mm) {
            float a8[8], b8[8];
            #pragma unroll
            for (int ii = 0; ii < 8; ++ii) a8[ii] = qs[(r0 + ii) * 68 + mm];
            #pragma unroll
            for (int jj = 0; jj < 8; ++jj) b8[jj] = ks[(j0 + jj * 16) * 68 + mm];
            #pragma unroll
            for (int ii = 0; ii < 8; ++ii)
                #pragma unroll
                for (int jj = 0; jj < 8; ++jj)
                    acc[ii * 8 + jj] = fmaf(a8[ii], b8[jj], acc[ii * 8 + jj]);
        }
        if (tid < 128) {
            #pragma unroll 4
            for (int mm = 0; mm < 64; ++mm) {
                float qv = qs[tid * 68 + mm];
                qzr = fmaf(qv, zs[mt * 64 + mm], qzr);
                sqr += qv;
            }
        }
    }
    if (tid < 128) { qz[tid] = qzr; sq[tid] = sqr; }

    // write masked scores
    #pragma unroll
    for (int ii = 0; ii < 8; ++ii) {
        int rr = r0 + ii;
        #pragma unroll
        for (int jj = 0; jj < 8; ++jj) {
            int jc = j0 + jj * 16;
            sc[rr * 132 + jc] = (jc <= rr) ? acc[ii * 8 + jj] : 0.f;
        }
    }
    __syncthreads();
    {
        int r = tid >> 1, h = tid & 1;
        float s = 0.f;
        #pragma unroll 4
        for (int t2 = 0; t2 < 64; ++t2) s += sc[r * 132 + h * 64 + t2];
        ss2[tid] = s;
    }
    __syncthreads();

    // ---- Phase 2: load v into ks buffer ----
    {
        const float4* vg4 = reinterpret_cast<const float4*>(vin) + base_row * 16;
        #pragma unroll
        for (int i = 0; i < 8; ++i) {
            int idx = tid + i * 256;
            int r = idx >> 4, c4 = idx & 15;
            *reinterpret_cast<float4*>(ks + r * 68 + c4 * 4) = vg4[idx];
        }
    }

    // thread -> 4 rows x 8 e (e strided by 8)
    const int rg = tid >> 3, eg = tid & 7;
    float oa[32];
    #pragma unroll
    for (int i = 0; i < 32; ++i) oa[i] = 0.f;
    const float* Sgp = g_S + (size_t)cix * MFEAT * EDIM;
    const float4* Sg4 = reinterpret_cast<const float4*>(Sgp);

    for (int mt = 0; mt < 4; ++mt) {
        __syncthreads();
        #pragma unroll
        for (int i = 0; i < 8; ++i) {
            int idx = tid + i * 256;
            int r = idx >> 4, c4 = idx & 15;
            *reinterpret_cast<float4*>(qs + r * 68 + c4 * 4) = gq4[(size_t)r * 64 + mt * 16 + c4];
        }
        #pragma unroll
        for (int i = 0; i < 4; ++i) {
            int idx = tid + i * 256;
            int e = idx >> 4, c4 = idx & 15;
            *reinterpret_cast<float4*>(Ss + e * 68 + c4 * 4) = Sg4[(size_t)e * 64 + mt * 16 + c4];
        }
        __syncthreads();
        #pragma unroll 4
        for (int mm = 0; mm < 64; ++mm) {
            float a4[4], s8[8];
            #pragma unroll
            for (int i = 0; i < 4; ++i) a4[i] = qs[(rg * 4 + i) * 68 + mm];
            #pragma unroll
            for (int j = 0; j < 8; ++j) s8[j] = Ss[(eg + j * 8) * 68 + mm];
            #pragma unroll
            for (int i = 0; i < 4; ++i)
                #pragma unroll
                for (int j = 0; j < 8; ++j)
                    oa[i * 8 + j] = fmaf(a4[i], s8[j], oa[i * 8 + j]);
        }
    }

    // intra: scores @ v
    #pragma unroll 2
    for (int j = 0; j < 128; ++j) {
        float a4[4], v8[8];
        #pragma unroll
        for (int i = 0; i < 4; ++i) a4[i] = sc[(rg * 4 + i) * 132 + j];
        #pragma unroll
        for (int jj = 0; jj < 8; ++jj) v8[jj] = ks[j * 68 + eg + jj * 8];
        #pragma unroll
        for (int i = 0; i < 4; ++i)
            #pragma unroll
            for (int jj = 0; jj < 8; ++jj)
                oa[i * 8 + jj] = fmaf(a4[i], v8[jj], oa[i * 8 + jj]);
    }

    // denom + store
    float* op = outp + base_row * EDIM;
    #pragma unroll
    for (int i = 0; i < 4; ++i) {
        int r = rg * 4 + i;
        float den = qz[r] + ss2[2 * r] + ss2[2 * r + 1] + EPS_DF * sq[r];
        float inv = 1.f / den;
        #pragma unroll
        for (int jj = 0; jj < 8; ++jj)
            op[(size_t)r * EDIM + eg + jj * 8] = oa[i * 8 + jj] * inv;
    }
}

// ---------------------------------------------------------------------------
extern "C" void kernel_launch(void* const* d_in, const int* in_sizes, int n_in,
                              void* d_out, int out_size) {
    // map inputs: three 4.2M tensors (q,k,v in order) + one 16384 proj
    const float* big[3] = {nullptr, nullptr, nullptr};
    const float* proj = nullptr;
    int nb = 0;
    for (int i = 0; i < n_in; ++i) {
        if (in_sizes[i] == MFEAT * DDIM) proj = (const float*)d_in[i];
        else if (nb < 3) big[nb++] = (const float*)d_in[i];
    }
    const float* q = big[0];
    const float* k = big[1];
    const float* v = big[2];
    float* out = (float*)d_out;

    cudaFuncSetAttribute(phi_kernel, cudaFuncAttributeMaxDynamicSharedMemorySize,
                         PHI_SMEM_FLOATS * (int)sizeof(float));
    cudaFuncSetAttribute(out_kernel, cudaFuncAttributeMaxDynamicSharedMemorySize,
                         OUT_SMEM_FLOATS * (int)sizeof(float));

    init_kmax_kernel<<<1, 32>>>();
    phi_kernel<<<BHC * NSEQ / 16, 256, PHI_SMEM_FLOATS * sizeof(float)>>>(q, proj, 1);
    phi_kernel<<<BHC * NSEQ / 16, 256, PHI_SMEM_FLOATS * sizeof(float)>>>(k, proj, 0);
    finalize_k_kernel<<<4096, 256>>>();
    chunk_sums_kernel<<<BHC * NCH, 256>>>(v);
    prefix_kernel<<<(BHC * MFEAT * EDIM + BHC * MFEAT) / 256, 256>>>();
    out_kernel<<<BHC * NCH, 256, OUT_SMEM_FLOATS * sizeof(float)>>>(v, out);
}

// round 6
// speedup vs baseline: 1.4595x; 1.4595x over previous
#include <cuda_runtime.h>
#include <cuda_bf16.h>
#include <cstdint>
#include <math.h>

// Problem constants
#define BHC   16
#define NSEQ  4096
#define DDIM  64
#define MFEAT 256
#define EDIM  64
#define CHK   128
#define NCH   32

#define NORM_F   0.35355339059327373f
#define DIAG_C   0.0625f
#define RATIO_F  0.0625f
#define EPS_KF   1e-4f
#define EPS_DF   1e-6f

// Scratch (static device globals)
__device__ float    g_phi_q[BHC * NSEQ * MFEAT];   // 64 MiB
__device__ float    g_phi_k[BHC * NSEQ * MFEAT];   // 64 MiB
__device__ float    g_S[BHC * NCH * MFEAT * EDIM]; // 32 MiB, per chunk [m 256][e 64]
__device__ float    g_z[BHC * NCH * MFEAT];
__device__ unsigned g_kmax[BHC];

// ---------------------------------------------------------------------------
__device__ __forceinline__ float tf32r(float x) {
    uint32_t u;
    asm("cvt.rna.tf32.f32 %0, %1;" : "=r"(u) : "f"(x));
    return __uint_as_float(u);
}
#define F2U(x) __float_as_uint(x)

__device__ __forceinline__ void mma8(float* c, uint32_t a0, uint32_t a1,
                                     uint32_t a2, uint32_t a3,
                                     uint32_t b0, uint32_t b1) {
    asm volatile("mma.sync.aligned.m16n8k8.row.col.f32.tf32.tf32.f32 "
                 "{%0,%1,%2,%3},{%4,%5,%6,%7},{%8,%9},{%0,%1,%2,%3};"
                 : "+f"(c[0]), "+f"(c[1]), "+f"(c[2]), "+f"(c[3])
                 : "r"(a0), "r"(a1), "r"(a2), "r"(a3), "r"(b0), "r"(b1));
}

// ---------------------------------------------------------------------------
__global__ void init_kmax_kernel() {
    if (threadIdx.x < BHC) g_kmax[threadIdx.x] = 0u;
}

// ---------------------------------------------------------------------------
// phi kernel: fp32. query -> g_phi_q (full phi); key -> g_phi_k (dd - diag)
#define PHI_SMEM_FLOATS (64 * 257 + 16 * 64)
__global__ void phi_kernel(const float* __restrict__ data,
                           const float* __restrict__ proj,
                           int is_query) {
    extern __shared__ float sm[];
    float* proj_s = sm;
    float* q_s    = sm + 64 * 257;
    __shared__ float wmax_s[8];

    const int tid = threadIdx.x;
    const int row0 = blockIdx.x * 16;

    #pragma unroll 4
    for (int i = 0; i < 64; ++i) {
        int idx = tid + i * 256;
        int j = idx >> 6, d = idx & 63;
        proj_s[d * 257 + j] = proj[idx] * NORM_F;
    }
    #pragma unroll
    for (int i = 0; i < 4; ++i) {
        int idx = tid + i * 256;
        q_s[idx] = data[(size_t)row0 * DDIM + idx];
    }
    __syncthreads();

    const int w = tid >> 5, lane = tid & 31;
    float wmax = -3.4e38f;

    #pragma unroll
    for (int rr = 0; rr < 2; ++rr) {
        const int rl = w * 2 + rr;
        const size_t rowg = (size_t)row0 + rl;
        float acc[8];
        #pragma unroll
        for (int jj = 0; jj < 8; ++jj) acc[jj] = 0.f;
        float ss = 0.f;
        #pragma unroll 4
        for (int d = 0; d < 64; ++d) {
            float qv = q_s[rl * 64 + d];
            ss = fmaf(qv, qv, ss);
            #pragma unroll
            for (int jj = 0; jj < 8; ++jj)
                acc[jj] = fmaf(qv, proj_s[d * 257 + jj * 32 + lane], acc[jj]);
        }
        const float diag = DIAG_C * ss;
        float m8 = acc[0];
        #pragma unroll
        for (int jj = 1; jj < 8; ++jj) m8 = fmaxf(m8, acc[jj]);

        if (is_query) {
            #pragma unroll
            for (int o = 16; o > 0; o >>= 1)
                m8 = fmaxf(m8, __shfl_xor_sync(0xffffffffu, m8, o));
            #pragma unroll
            for (int jj = 0; jj < 8; ++jj)
                g_phi_q[rowg * MFEAT + jj * 32 + lane] =
                    RATIO_F * (expf(acc[jj] - diag - m8) + EPS_KF);
        } else {
            #pragma unroll
            for (int jj = 0; jj < 8; ++jj)
                g_phi_k[rowg * MFEAT + jj * 32 + lane] = acc[jj] - diag;
            wmax = fmaxf(wmax, m8);
        }
    }

    if (!is_query) {
        #pragma unroll
        for (int o = 16; o > 0; o >>= 1)
            wmax = fmaxf(wmax, __shfl_xor_sync(0xffffffffu, wmax, o));
        if (lane == 0) wmax_s[w] = wmax;
        __syncthreads();
        if (tid == 0) {
            float bm = wmax_s[0];
            #pragma unroll
            for (int i = 1; i < 8; ++i) bm = fmaxf(bm, wmax_s[i]);
            unsigned u = __float_as_uint(bm);
            u = (u & 0x80000000u) ? ~u : (u | 0x80000000u);
            atomicMax(&g_kmax[blockIdx.x >> 8], u);
        }
    }
}

// ---------------------------------------------------------------------------
// finalize phi_k: in-place exp with global per-bh max
__global__ void finalize_k_kernel() {
    const size_t n4 = (size_t)BHC * NSEQ * MFEAT / 4;
    float4* p = reinterpret_cast<float4*>(g_phi_k);
    const size_t stride = (size_t)gridDim.x * blockDim.x;
    for (size_t t = (size_t)blockIdx.x * blockDim.x + threadIdx.x; t < n4; t += stride) {
        size_t bh = (t * 4) / ((size_t)NSEQ * MFEAT);
        unsigned u = g_kmax[bh];
        float mx = __uint_as_float((u & 0x80000000u) ? (u ^ 0x80000000u) : ~u);
        float4 v = p[t];
        v.x = RATIO_F * (expf(v.x - mx) + EPS_KF);
        v.y = RATIO_F * (expf(v.y - mx) + EPS_KF);
        v.z = RATIO_F * (expf(v.z - mx) + EPS_KF);
        v.w = RATIO_F * (expf(v.w - mx) + EPS_KF);
        p[t] = v;
    }
}

// ---------------------------------------------------------------------------
// chunk sums via mma: C[m=256, e=64(+z)] = phik^T[m, r=128] @ [v | 1][r, 72]
// smem: ksm [128 r][264] (sigma=8), vsm [128 r][72] (sigma=8)
#define CK_KS   0
#define CK_VS   (128 * 264)
#define CK_SMEMF (CK_VS + 128 * 72)
__global__ void __launch_bounds__(256, 1)
chunk_mma_kernel(const float* __restrict__ vin) {
    extern __shared__ float sf[];
    float* ksm = sf + CK_KS;
    float* vsm = sf + CK_VS;

    const int tid = threadIdx.x;
    const int wid = tid >> 5, lane = tid & 31;
    const int tq = lane >> 2, tr = lane & 3;   // fragment row/col ids
    const int qr = lane >> 3, qc = lane & 7;   // staging quarter mapping
    const int cix = blockIdx.x;
    const size_t base_row = (size_t)(cix / NCH) * NSEQ + (size_t)(cix % NCH) * CHK;

    // stage phi_k [128][256] fp32 -> tf32
    {
        const float4* src = reinterpret_cast<const float4*>(g_phi_k + base_row * MFEAT);
        #pragma unroll
        for (int j = 0; j < 4; ++j) {
            int r = wid * 4 + qr + 32 * j;
            #pragma unroll
            for (int i = 0; i < 8; ++i) {
                int c4 = qc + 8 * i;
                float4 t = src[r * 64 + c4];
                t.x = tf32r(t.x); t.y = tf32r(t.y); t.z = tf32r(t.z); t.w = tf32r(t.w);
                *reinterpret_cast<float4*>(ksm + r * 264 + 4 * c4) = t;
            }
        }
    }
    // stage v [128][64] + ones column
    {
        const float4* src = reinterpret_cast<const float4*>(vin + base_row * EDIM);
        #pragma unroll
        for (int j = 0; j < 4; ++j) {
            int r = wid * 4 + qr + 32 * j;
            #pragma unroll
            for (int i = 0; i < 2; ++i) {
                int c4 = qc + 8 * i;
                float4 t = src[r * 16 + c4];
                t.x = tf32r(t.x); t.y = tf32r(t.y); t.z = tf32r(t.z); t.w = tf32r(t.w);
                *reinterpret_cast<float4*>(vsm + r * 72 + 4 * c4) = t;
            }
        }
        if (tid < 128) {
            *reinterpret_cast<float4*>(vsm + tid * 72 + 64) = make_float4(1.f, 0.f, 0.f, 0.f);
            *reinterpret_cast<float4*>(vsm + tid * 72 + 68) = make_float4(0.f, 0.f, 0.f, 0.f);
        }
    }
    __syncthreads();

    const int m0 = wid * 32;
    float acc[2][9][4];
    #pragma unroll
    for (int mt = 0; mt < 2; ++mt)
        #pragma unroll
        for (int nt = 0; nt < 9; ++nt)
            #pragma unroll
            for (int i = 0; i < 4; ++i) acc[mt][nt][i] = 0.f;

    #pragma unroll 4
    for (int ks = 0; ks < 16; ++ks) {
        const int k0 = ks * 8;
        uint32_t b0[9], b1[9];
        #pragma unroll
        for (int nt = 0; nt < 9; ++nt) {
            b0[nt] = F2U(vsm[(k0 + tr) * 72 + nt * 8 + tq]);
            b1[nt] = F2U(vsm[(k0 + tr + 4) * 72 + nt * 8 + tq]);
        }
        #pragma unroll
        for (int mt = 0; mt < 2; ++mt) {
            const int mb = m0 + mt * 16;
            uint32_t a0 = F2U(ksm[(k0 + tr) * 264 + mb + tq]);
            uint32_t a1 = F2U(ksm[(k0 + tr) * 264 + mb + tq + 8]);
            uint32_t a2 = F2U(ksm[(k0 + tr + 4) * 264 + mb + tq]);
            uint32_t a3 = F2U(ksm[(k0 + tr + 4) * 264 + mb + tq + 8]);
            #pragma unroll
            for (int nt = 0; nt < 9; ++nt)
                mma8(acc[mt][nt], a0, a1, a2, a3, b0[nt], b1[nt]);
        }
    }

    float* Sg = g_S + (size_t)cix * MFEAT * EDIM;
    float* zg = g_z + (size_t)cix * MFEAT;
    #pragma unroll
    for (int mt = 0; mt < 2; ++mt) {
        int m = m0 + mt * 16 + tq;
        #pragma unroll
        for (int nt = 0; nt < 8; ++nt) {
            int c0 = nt * 8 + 2 * tr;
            *reinterpret_cast<float2*>(Sg + m * EDIM + c0)
                = make_float2(acc[mt][nt][0], acc[mt][nt][1]);
            *reinterpret_cast<float2*>(Sg + (m + 8) * EDIM + c0)
                = make_float2(acc[mt][nt][2], acc[mt][nt][3]);
        }
        if (tr == 0) {
            zg[m]     = acc[mt][8][0];
            zg[m + 8] = acc[mt][8][2];
        }
    }
}

// ---------------------------------------------------------------------------
__global__ void prefix_kernel() {
    const int idx = blockIdx.x * blockDim.x + threadIdx.x;
    const int T1 = BHC * MFEAT * EDIM;
    if (idx < T1) {
        int bh = idx / (MFEAT * EDIM);
        int rem = idx % (MFEAT * EDIM);
        size_t base = (size_t)bh * NCH * MFEAT * EDIM + rem;
        float run = 0.f;
        #pragma unroll
        for (int c = 0; c < NCH; ++c) {
            size_t p = base + (size_t)c * MFEAT * EDIM;
            float t = g_S[p]; g_S[p] = run; run += t;
        }
    } else if (idx < T1 + BHC * MFEAT) {
        int j = idx - T1;
        int bh = j / MFEAT;
        int rem = j % MFEAT;
        size_t base = (size_t)bh * NCH * MFEAT + rem;
        float run = 0.f;
        #pragma unroll
        for (int c = 0; c < NCH; ++c) {
            size_t p = base + (size_t)c * MFEAT;
            float t = g_z[p]; g_z[p] = run; run += t;
        }
    }
}

// ---------------------------------------------------------------------------
// out kernel (tf32 mma): per (bh, chunk)
//   scores[128,128] = phiq @ phik^T (K=256, 2 halves), inter[128,64] = phiq @ S_prev
//   intra accumulates onto inter with A = tril-masked scores, B = v
//   denom = q.z_prev + rowsum(tril scores) + EPS*sum(q)
#define SA 140               // sigma = 12: conflict-free for 8x4 fragments
#define SB 72                // sigma = 8 : conflict-free for 4x8 fragments
#define BUFA 0               // phi_q half / masked scores  [128][140]
#define BUFB (128 * SA)      // phi_k half / v              [128][140] (v uses [128][72])
#define BUFS (2 * 128 * SA)  // S half [128][72]
#define ZSO  (BUFS + 128 * SB)
#define QZ2O (ZSO + 256)
#define SQ2O (QZ2O + 256)
#define SUMO (SQ2O + 256)
#define DENO (SUMO + 128)
#define OUT_SMEMF (DENO + 128)

__global__ void __launch_bounds__(256, 1)
out_mma_kernel(const float* __restrict__ vin, float* __restrict__ outp) {
    extern __shared__ float sf[];
    float* bufA = sf + BUFA;
    float* bufB = sf + BUFB;
    float* bufS = sf + BUFS;
    float* zs   = sf + ZSO;
    float* qz2  = sf + QZ2O;
    float* sq2  = sf + SQ2O;
    float* sums = sf + SUMO;
    float* den  = sf + DENO;

    const int tid = threadIdx.x;
    const int wid = tid >> 5, lane = tid & 31;
    const int tq = lane >> 2, tr = lane & 3;
    const int qr = lane >> 3, qc = lane & 7;
    const int cix = blockIdx.x;
    const size_t base_row = (size_t)(cix / NCH) * NSEQ + (size_t)(cix % NCH) * CHK;
    const int m0 = wid * 16;

    zs[tid] = g_z[(size_t)cix * MFEAT + tid];

    float sacc[16][4];
    float iacc[8][4];
    #pragma unroll
    for (int nt = 0; nt < 16; ++nt)
        #pragma unroll
        for (int i = 0; i < 4; ++i) sacc[nt][i] = 0.f;
    #pragma unroll
    for (int nt = 0; nt < 8; ++nt)
        #pragma unroll
        for (int i = 0; i < 4; ++i) iacc[nt][i] = 0.f;

    float qzr = 0.f, sqr = 0.f;
    const float4* gq4 = reinterpret_cast<const float4*>(g_phi_q + base_row * MFEAT);
    const float4* gk4 = reinterpret_cast<const float4*>(g_phi_k + base_row * MFEAT);

    for (int h = 0; h < 2; ++h) {
        __syncthreads();
        // stage phi_q / phi_k halves [128][128] (+ S half [128][64])
        const float4* Sg4 = reinterpret_cast<const float4*>(
            g_S + (size_t)cix * MFEAT * EDIM + (size_t)h * 128 * EDIM);
        #pragma unroll
        for (int j = 0; j < 4; ++j) {
            int r = wid * 4 + qr + 32 * j;
            #pragma unroll
            for (int i = 0; i < 4; ++i) {
                int c4 = qc + 8 * i;
                float4 tA = gq4[r * 64 + h * 32 + c4];
                float4 tB = gk4[r * 64 + h * 32 + c4];
                tA.x = tf32r(tA.x); tA.y = tf32r(tA.y); tA.z = tf32r(tA.z); tA.w = tf32r(tA.w);
                tB.x = tf32r(tB.x); tB.y = tf32r(tB.y); tB.z = tf32r(tB.z); tB.w = tf32r(tB.w);
                *reinterpret_cast<float4*>(bufA + r * SA + 4 * c4) = tA;
                *reinterpret_cast<float4*>(bufB + r * SA + 4 * c4) = tB;
            }
            #pragma unroll
            for (int i = 0; i < 2; ++i) {
                int c4 = qc + 8 * i;
                float4 tS = Sg4[r * 16 + c4];
                tS.x = tf32r(tS.x); tS.y = tf32r(tS.y); tS.z = tf32r(tS.z); tS.w = tf32r(tS.w);
                *reinterpret_cast<float4*>(bufS + r * SB + 4 * c4) = tS;
            }
        }
        __syncthreads();

        #pragma unroll 2
        for (int ks = 0; ks < 16; ++ks) {
            const int k0 = ks * 8;
            uint32_t a0 = F2U(bufA[(m0 + tq) * SA + k0 + tr]);
            uint32_t a1 = F2U(bufA[(m0 + tq + 8) * SA + k0 + tr]);
            uint32_t a2 = F2U(bufA[(m0 + tq) * SA + k0 + tr + 4]);
            uint32_t a3 = F2U(bufA[(m0 + tq + 8) * SA + k0 + tr + 4]);
            #pragma unroll
            for (int nt = 0; nt < 16; ++nt) {
                uint32_t b0 = F2U(bufB[(nt * 8 + tq) * SA + k0 + tr]);
                uint32_t b1 = F2U(bufB[(nt * 8 + tq) * SA + k0 + tr + 4]);
                mma8(sacc[nt], a0, a1, a2, a3, b0, b1);
            }
            #pragma unroll
            for (int nt = 0; nt < 8; ++nt) {
                uint32_t b0 = F2U(bufS[(k0 + tr) * SB + nt * 8 + tq]);
                uint32_t b1 = F2U(bufS[(k0 + tr + 4) * SB + nt * 8 + tq]);
                mma8(iacc[nt], a0, a1, a2, a3, b0, b1);
            }
        }
        // qz/sq partials from staged phi_q half
        {
            const float* pq = bufA + (tid >> 1) * SA + (tid & 1) * 64;
            const float* pz = zs + h * 128 + (tid & 1) * 64;
            #pragma unroll 8
            for (int j = 0; j < 64; ++j) {
                qzr = fmaf(pq[j], pz[j], qzr);
                sqr += pq[j];
            }
        }
    }

    __syncthreads();   // all warps done with bufA/bufB before overwrite

    // epilogue: masked scores -> bufA (as sc), rowsums -> sums
    const int rlo = m0 + tq, rhi = rlo + 8;
    {
        float rsl = 0.f, rsh = 0.f;
        #pragma unroll
        for (int nt = 0; nt < 16; ++nt) {
            int c0 = nt * 8 + 2 * tr;
            float s0 = (c0     <= rlo) ? sacc[nt][0] : 0.f;
            float s1 = (c0 + 1 <= rlo) ? sacc[nt][1] : 0.f;
            float s2 = (c0     <= rhi) ? sacc[nt][2] : 0.f;
            float s3 = (c0 + 1 <= rhi) ? sacc[nt][3] : 0.f;
            rsl += s0 + s1; rsh += s2 + s3;
            *reinterpret_cast<float2*>(bufA + rlo * SA + c0) = make_float2(tf32r(s0), tf32r(s1));
            *reinterpret_cast<float2*>(bufA + rhi * SA + c0) = make_float2(tf32r(s2), tf32r(s3));
        }
        rsl += __shfl_xor_sync(0xffffffffu, rsl, 1);
        rsl += __shfl_xor_sync(0xffffffffu, rsl, 2);
        rsh += __shfl_xor_sync(0xffffffffu, rsh, 1);
        rsh += __shfl_xor_sync(0xffffffffu, rsh, 2);
        if (tr == 0) { sums[rlo] = rsl; sums[rhi] = rsh; }
    }
    // stage v -> bufB (stride SB)
    {
        const float4* vg4 = reinterpret_cast<const float4*>(vin + base_row * EDIM);
        #pragma unroll
        for (int j = 0; j < 4; ++j) {
            int r = wid * 4 + qr + 32 * j;
            #pragma unroll
            for (int i = 0; i < 2; ++i) {
                int c4 = qc + 8 * i;
                float4 t = vg4[r * 16 + c4];
                t.x = tf32r(t.x); t.y = tf32r(t.y); t.z = tf32r(t.z); t.w = tf32r(t.w);
                *reinterpret_cast<float4*>(bufB + r * SB + 4 * c4) = t;
            }
        }
    }
    qz2[tid] = qzr; sq2[tid] = sqr;
    __syncthreads();

    if (tid < 128) {
        float d = qz2[2 * tid] + qz2[2 * tid + 1] + sums[tid]
                + EPS_DF * (sq2[2 * tid] + sq2[2 * tid + 1]);
        den[tid] = 1.f / d;
    }

    // intra: iacc += masked_scores @ v   (A = bufA, B = bufB stride SB)
    #pragma unroll 2
    for (int ks = 0; ks < 16; ++ks) {
        const int k0 = ks * 8;
        uint32_t a0 = F2U(bufA[(m0 + tq) * SA + k0 + tr]);
        uint32_t a1 = F2U(bufA[(m0 + tq + 8) * SA + k0 + tr]);
        uint32_t a2 = F2U(bufA[(m0 + tq) * SA + k0 + tr + 4]);
        uint32_t a3 = F2U(bufA[(m0 + tq + 8) * SA + k0 + tr + 4]);
        #pragma unroll
        for (int nt = 0; nt < 8; ++nt) {
            uint32_t b0 = F2U(bufB[(k0 + tr) * SB + nt * 8 + tq]);
            uint32_t b1 = F2U(bufB[(k0 + tr + 4) * SB + nt * 8 + tq]);
            mma8(iacc[nt], a0, a1, a2, a3, b0, b1);
        }
    }
    __syncthreads();

    // final: out = iacc * inv_den
    {
        float il = den[rlo], ih = den[rhi];
        float* olo = outp + (base_row + rlo) * EDIM;
        float* ohi = outp + (base_row + rhi) * EDIM;
        #pragma unroll
        for (int nt = 0; nt < 8; ++nt) {
            int c0 = nt * 8 + 2 * tr;
            *reinterpret_cast<float2*>(olo + c0) = make_float2(iacc[nt][0] * il, iacc[nt][1] * il);
            *reinterpret_cast<float2*>(ohi + c0) = make_float2(iacc[nt][2] * ih, iacc[nt][3] * ih);
        }
    }
}

// ---------------------------------------------------------------------------
extern "C" void kernel_launch(void* const* d_in, const int* in_sizes, int n_in,
                              void* d_out, int out_size) {
    const float* big[3] = {nullptr, nullptr, nullptr};
    const float* proj = nullptr;
    int nb = 0;
    for (int i = 0; i < n_in; ++i) {
        if (in_sizes[i] == MFEAT * DDIM) proj = (const float*)d_in[i];
        else if (nb < 3) big[nb++] = (const float*)d_in[i];
    }
    const float* q = big[0];
    const float* k = big[1];
    const float* v = big[2];
    float* out = (float*)d_out;

    cudaFuncSetAttribute(phi_kernel, cudaFuncAttributeMaxDynamicSharedMemorySize,
                         PHI_SMEM_FLOATS * (int)sizeof(float));
    cudaFuncSetAttribute(chunk_mma_kernel, cudaFuncAttributeMaxDynamicSharedMemorySize,
                         CK_SMEMF * (int)sizeof(float));
    cudaFuncSetAttribute(out_mma_kernel, cudaFuncAttributeMaxDynamicSharedMemorySize,
                         OUT_SMEMF * (int)sizeof(float));

    init_kmax_kernel<<<1, 32>>>();
    phi_kernel<<<BHC * NSEQ / 16, 256, PHI_SMEM_FLOATS * sizeof(float)>>>(q, proj, 1);
    phi_kernel<<<BHC * NSEQ / 16, 256, PHI_SMEM_FLOATS * sizeof(float)>>>(k, proj, 0);
    finalize_k_kernel<<<4096, 256>>>();
    chunk_mma_kernel<<<BHC * NCH, 256, CK_SMEMF * sizeof(float)>>>(v);
    prefix_kernel<<<(BHC * MFEAT * EDIM + BHC * MFEAT) / 256, 256>>>();
    out_mma_kernel<<<BHC * NCH, 256, OUT_SMEMF * sizeof(float)>>>(v, out);
}